// round 14
// baseline (speedup 1.0000x reference)
#include <cuda_runtime.h>
#include <cuda_bf16.h>
#include <cstdint>

// Problem constants
#define HW_N   262144      // H*W
#define KN     512         // num_embeddings
#define DN     64          // embedding_dim
#define EMA_D  0.99f
#define EPS    1e-5f

// Output layout (reference return order, all fp32):
#define O_ZQ    0               // z_q_st   [H,W,D] 16777216
#define O_IDX   16777216        // indices  [H,W]     262144
#define O_MIND  17039360        // min_dist [N]       262144
#define O_CB    17301504        // new_codebook [K,D]  32768
#define O_CS    17334272        // new_ema_cluster [K]   512
#define O_SUM   17334784        // new_ema_emb_sum [K,D] 32768

// Scratch (zero-initialized at module load; last block re-zeros each launch)
__device__ float g_counts[KN];
__device__ float g_sums[KN * DN];
__device__ unsigned int g_done;

// packed fp32x2 FMA (SASS FFMA2) — 2x fp32 throughput (approx path only)
__device__ __forceinline__ unsigned long long fma2(unsigned long long a,
                                                   unsigned long long b,
                                                   unsigned long long c) {
    unsigned long long d;
    asm("fma.rn.f32x2 %0, %1, %2, %3;" : "=l"(d) : "l"(a), "l"(b), "l"(c));
    return d;
}
__device__ __forceinline__ float sum2(unsigned long long a) {
    unsigned int lo, hi;
    asm("mov.b64 {%0, %1}, %2;" : "=r"(lo), "=r"(hi) : "l"(a));
    return __uint_as_float(lo) + __uint_as_float(hi);
}

// ---------------------------------------------------------------------------
// ONE fused kernel: bsq + distances (f32x2 FFMA2, 8x8 microtile) + top-2 +
// exact recheck + z_q/EMA epilogue + last-block EMA finalization.
//   1024 blocks x 128 threads, 256 points/block.
//   tx = tid&3 (4 k-lanes), ty = tid>>2 (32 point-lanes).
//   Codebook chunks of 32 double-buffered in smem, one barrier per chunk.
// ---------------------------------------------------------------------------
#define ZS    68          // smem row pitch (floats): 16B-aligned, conflict-free
#define NPB   256
#define NBLK  (HW_N / NPB)   // 1024
// smem floats: zlin 256*68 | cbuf 2*32*68 | bsq 512 | asq 256 | c1,c2 256 ints
#define SMF (NPB*ZS + 2*32*ZS + KN + NPB + 2*NPB)
#define SMB (SMF * 4)        // 93184 B -> 2 CTAs/SM

__global__ __launch_bounds__(128)
void vq_fused(const float* __restrict__ z_e,
              const float* __restrict__ cb,
              const float* __restrict__ ema_cs,
              const float* __restrict__ ema_sum,
              float* __restrict__ out) {
    extern __shared__ float sm[];
    float* zlin = sm;                      // [256][68]
    float* cbuf = zlin + NPB * ZS;         // [2][32][68]
    float* bsq  = cbuf + 2 * 32 * ZS;      // [512]
    float* asq  = bsq + KN;                // [256]
    int*   c1   = (int*)(asq + NPB);       // [256]
    int*   c2   = c1 + NPB;                // [256]

    const int tid = threadIdx.x;
    const int tx  = tid & 3;
    const int ty  = tid >> 2;
    const int pbase = blockIdx.x * NPB;

    // ---- prologue: z tile (32 float4 slots/thread)
#pragma unroll
    for (int i = 0; i < 32; i++) {
        int e = tid + i * 128;
        int row = e >> 4, c4 = e & 15;
        float4 v = *(const float4*)(z_e + (size_t)(pbase + row) * DN + c4 * 4);
        *(float4*)&zlin[row * ZS + c4 * 4] = v;
    }
    // chunk 0 -> buf0 (4 slots/thread)
#pragma unroll
    for (int i = 0; i < 4; i++) {
        int s = tid + i * 128;
        int row = s >> 4, c4 = s & 15;
        float4 v = *(const float4*)(cb + (size_t)row * DN + c4 * 4);
        *(float4*)&cbuf[row * ZS + c4 * 4] = v;
    }
    // bsq: strict sequential rn(s + rn(c*c)) — 4 rows/thread (validated order)
#pragma unroll
    for (int r = 0; r < 4; r++) {
        int row = tid + r * 128;
        const float4* rp = (const float4*)(cb + (size_t)row * DN);
        float4 v[16];
#pragma unroll
        for (int i = 0; i < 16; i++) v[i] = rp[i];
        float s = 0.0f;
#pragma unroll
        for (int i = 0; i < 16; i++) {
            s = __fadd_rn(s, __fmul_rn(v[i].x, v[i].x));
            s = __fadd_rn(s, __fmul_rn(v[i].y, v[i].y));
            s = __fadd_rn(s, __fmul_rn(v[i].z, v[i].z));
            s = __fadd_rn(s, __fmul_rn(v[i].w, v[i].w));
        }
        bsq[row] = s;
    }
    __syncthreads();

    // a_sq for 2 points/thread (strict sequential, validated)
#pragma unroll
    for (int r = 0; r < 2; r++) {
        int p = tid + r * 128;
        float s = 0.0f;
#pragma unroll
        for (int d = 0; d < DN; d++) {
            float v = zlin[p * ZS + d];
            s = __fadd_rn(s, __fmul_rn(v, v));
        }
        asq[p] = s;
    }

    // ---- mainloop: top-2 per point (8 points/thread), f32x2 microtile
    float v1[8], v2[8];
    int   i1[8], i2[8];
#pragma unroll
    for (int pp = 0; pp < 8; pp++) {
        v1[pp] = 3.4e38f; v2[pp] = 3.4e38f; i1[pp] = KN; i2[pp] = KN;
    }

    for (int c = 0; c < 16; c++) {
        float* buf = cbuf + (c & 1) * 32 * ZS;
        // early LDG+STS of next chunk into the other buffer (latency covered
        // by co-resident warps' FMA work; prev iter's readers of this buffer
        // are past the last barrier)
        if (c + 1 < 16) {
            float* nb = cbuf + ((c + 1) & 1) * 32 * ZS;
            const float* cbn = cb + (size_t)(c + 1) * 32 * DN;
#pragma unroll
            for (int i = 0; i < 4; i++) {
                int s = tid + i * 128;
                int row = s >> 4, c4 = s & 15;
                float4 v = *(const float4*)(cbn + (size_t)row * DN + c4 * 4);
                *(float4*)&nb[row * ZS + c4 * 4] = v;
            }
        }

        unsigned long long acc[8][8];
#pragma unroll
        for (int pp = 0; pp < 8; pp++)
#pragma unroll
            for (int kk = 0; kk < 8; kk++) acc[pp][kk] = 0ULL;

#pragma unroll
        for (int d4 = 0; d4 < DN / 4; d4++) {
            ulonglong2 zv[8];
#pragma unroll
            for (int pp = 0; pp < 8; pp++)
                zv[pp] = *(const ulonglong2*)&zlin[(pp * 32 + ty) * ZS + d4 * 4];
#pragma unroll
            for (int kk = 0; kk < 8; kk++) {
                ulonglong2 cv =
                    *(const ulonglong2*)&buf[(kk * 4 + tx) * ZS + d4 * 4];
#pragma unroll
                for (int pp = 0; pp < 8; pp++) {
                    acc[pp][kk] = fma2(zv[pp].x, cv.x, acc[pp][kk]);
                    acc[pp][kk] = fma2(zv[pp].y, cv.y, acc[pp][kk]);
                }
            }
        }

        // top-2 update (ascending k in-thread preserves ties-by-index)
#pragma unroll
        for (int kk = 0; kk < 8; kk++) {
            int kloc = kk * 4 + tx;
            int kg   = c * 32 + kloc;
            float b  = bsq[kg];
#pragma unroll
            for (int pp = 0; pp < 8; pp++) {
                float val = fmaf(-2.0f, sum2(acc[pp][kk]), b);
                if (val < v2[pp]) {
                    if (val < v1[pp]) {
                        v2[pp] = v1[pp]; i2[pp] = i1[pp];
                        v1[pp] = val;    i1[pp] = kg;
                    } else {
                        v2[pp] = val;    i2[pp] = kg;
                    }
                }
            }
        }
        __syncthreads();   // next-buffer STS visible; single barrier per chunk
    }

    // ---- merge top-2 across the 4 k-lanes (xor 2, 1)
#pragma unroll
    for (int off = 2; off >= 1; off >>= 1) {
#pragma unroll
        for (int pp = 0; pp < 8; pp++) {
            float ov1 = __shfl_xor_sync(0xFFFFFFFFu, v1[pp], off);
            int   oi1 = __shfl_xor_sync(0xFFFFFFFFu, i1[pp], off);
            float ov2 = __shfl_xor_sync(0xFFFFFFFFu, v2[pp], off);
            int   oi2 = __shfl_xor_sync(0xFFFFFFFFu, i2[pp], off);
            if (ov1 < v1[pp] || (ov1 == v1[pp] && oi1 < i1[pp])) {
                float nv2; int ni2;
                if (v1[pp] < ov2 || (v1[pp] == ov2 && i1[pp] < oi2)) {
                    nv2 = v1[pp]; ni2 = i1[pp];
                } else { nv2 = ov2; ni2 = oi2; }
                v1[pp] = ov1; i1[pp] = oi1;
                v2[pp] = nv2; i2[pp] = ni2;
            } else if (ov1 < v2[pp] || (ov1 == v2[pp] && oi1 < i2[pp])) {
                v2[pp] = ov1; i2[pp] = oi1;
            }
        }
    }
    if (tx == 0) {
#pragma unroll
        for (int pp = 0; pp < 8; pp++) {
            int p = pp * 32 + ty;
            c1[p] = i1[pp];
            c2[p] = i2[pp];
        }
    }
    __syncthreads();

    // ---- exact recheck (validated arithmetic) + epilogue, 2 points/thread
#pragma unroll
    for (int r = 0; r < 2; r++) {
        int p   = tid + r * 128;
        int ca  = c1[p];
        int cbi = c2[p];
        float as = asq[p];
        const float* rowa = cb + (size_t)ca  * DN;
        const float* rowb = cb + (size_t)cbi * DN;
        float da = 0.0f, db = 0.0f;
#pragma unroll
        for (int d = 0; d < DN; d++) {
            float z = zlin[p * ZS + d];
            da = fmaf(z, __ldg(rowa + d), da);
            db = fmaf(z, __ldg(rowb + d), db);
        }
        float va = __fadd_rn(__fsub_rn(as, __fmul_rn(2.0f, da)), bsq[ca]);
        float vb = __fadd_rn(__fsub_rn(as, __fmul_rn(2.0f, db)), bsq[cbi]);
        int wi; float wv;
        if (vb < va || (vb == va && cbi < ca)) { wi = cbi; wv = vb; }
        else                                    { wi = ca;  wv = va; }

        out[O_IDX  + pbase + p] = (float)wi;
        out[O_MIND + pbase + p] = wv;
        atomicAdd(&g_counts[wi], 1.0f);

        float* orow = out + O_ZQ + (size_t)(pbase + p) * DN;
        float* srow = g_sums + (size_t)wi * DN;
        const float* crow = cb + (size_t)wi * DN;
#pragma unroll
        for (int q = 0; q < 16; q++) {
            int d = q * 4;
            float4 z = *(const float4*)&zlin[p * ZS + d];
            float4 cc = *(const float4*)(crow + d);
            float4 rr;
            rr.x = __fadd_rn(z.x, __fsub_rn(cc.x, z.x));
            rr.y = __fadd_rn(z.y, __fsub_rn(cc.y, z.y));
            rr.z = __fadd_rn(z.z, __fsub_rn(cc.z, z.z));
            rr.w = __fadd_rn(z.w, __fsub_rn(cc.w, z.w));
            *(float4*)(orow + d) = rr;
            asm volatile("red.global.add.v4.f32 [%0], {%1, %2, %3, %4};"
                         :: "l"(srow + d), "f"(z.x), "f"(z.y), "f"(z.z), "f"(z.w)
                         : "memory");
        }
    }

    // ---- last-block EMA finalization + scratch re-zero for next replay
    __threadfence();
    __shared__ unsigned int lastflag;
    if (tid == 0) {
        unsigned int v = atomicAdd(&g_done, 1u);
        lastflag = (v == NBLK - 1) ? 1u : 0u;
    }
    __syncthreads();
    if (lastflag) {
        __threadfence();   // acquire: all blocks' atomics visible
        for (int k = tid; k < KN; k += 128) {
            float cs_new = __fadd_rn(__fmul_rn(EMA_D, ema_cs[k]),
                                     __fmul_rn(1.0f - EMA_D, g_counts[k]));
            out[O_CS + k] = cs_new;
            float den = __fadd_rn(cs_new, EPS);
#pragma unroll 4
            for (int d = 0; d < DN; d++) {
                float s_new = __fadd_rn(__fmul_rn(EMA_D, ema_sum[k * DN + d]),
                                        __fmul_rn(1.0f - EMA_D, g_sums[k * DN + d]));
                out[O_SUM + k * DN + d] = s_new;
                out[O_CB  + k * DN + d] = __fdiv_rn(s_new, den);
                g_sums[k * DN + d] = 0.0f;
            }
            g_counts[k] = 0.0f;
        }
        __syncthreads();
        if (tid == 0) g_done = 0u;
    }
}

// ---------------------------------------------------------------------------
extern "C" void kernel_launch(void* const* d_in, const int* in_sizes, int n_in,
                              void* d_out, int out_size) {
    const float* z_e      = (const float*)d_in[0];
    const float* codebook = (const float*)d_in[1];
    const float* ema_cs   = (const float*)d_in[2];
    const float* ema_sum  = (const float*)d_in[3];
    float* out = (float*)d_out;

    cudaFuncSetAttribute(vq_fused,
                         cudaFuncAttributeMaxDynamicSharedMemorySize, SMB);

    vq_fused<<<NBLK, 128, SMB>>>(z_e, codebook, ema_cs, ema_sum, out);
}